// round 5
// baseline (speedup 1.0000x reference)
#include <cuda_runtime.h>
#include <math.h>

// Problem constants (fixed by reference setup_inputs)
#define H    768
#define T    512
#define BS   32

// Persistent-grid config: 128 CTAs (<=148 SMs -> all co-resident, barrier is safe)
#define GRID  128
#define HPC   6            // h-indices per CTA (768/128)
#define NWARP 18           // 3 gates * HPC rows, one warp per row
#define NTHR  (NWARP*32)   // 576 threads

// Device scratch (allocation-free rule: __device__ globals)
__device__ unsigned g_ctr;            // global step barrier counter
__device__ float    g_hbuf[2][H];     // double-buffered hidden state
__device__ int      g_L[BS];          // per-sample effective lengths

// ---------------------------------------------------------------------------
// Kernel 1: compute L[b] = clamp(T - #zeros(mask[b]), <1 -> 2); also reset ctr
// NOTE: attention_mask is int32 on device (JAX demotes int64 without x64 mode).
// ---------------------------------------------------------------------------
__global__ void compute_L_kernel(const int* __restrict__ mask)
{
    if (threadIdx.x == 0) g_ctr = 0u;   // reset barrier counter for this launch
    int w = threadIdx.x >> 5, lane = threadIdx.x & 31;
    if (w < BS) {
        int zeros = 0;
        #pragma unroll
        for (int i = 0; i < T / 32; i++)
            zeros += (mask[w * T + lane + 32 * i] == 0);
        #pragma unroll
        for (int m = 16; m; m >>= 1) zeros += __shfl_xor_sync(~0u, zeros, m);
        if (lane == 0) {
            int L = T - zeros;
            if (L < 1) L = 2;
            g_L[w] = L;
        }
    }
}

// ---------------------------------------------------------------------------
// Kernel 2: persistent fused GRU chain.
// CTA c owns h-indices [c*HPC, c*HPC+HPC). Warp w handles gate g=w/HPC,
// local index j=w%HPC  -> weight row g*H + c*HPC + j.
// Lane l holds W[row][4l..] in registers for BOTH W_ih and W_hh.
// Per step: fused matvec (x and h), warp reduce, 6-lane gate combine,
// global double-buffered h broadcast via monotonic counter barrier.
// All cross-SM traffic (g_hbuf, g_ctr) uses L2-coherent accesses (.cg /
// volatile) -- plain LDG can hit a stale L1 line from 2 steps earlier.
// ---------------------------------------------------------------------------
__global__ void __launch_bounds__(NTHR, 1) gru_kernel(
    const float* __restrict__ emb,   // [BS, T, H]
    const float* __restrict__ gc,    // [H]
    const float* __restrict__ Wih,   // [3H, H]
    const float* __restrict__ Whh,   // [3H, H]
    const float* __restrict__ bih,   // [3H]
    const float* __restrict__ bhh,   // [3H]
    float* __restrict__ out, int out_size)
{
    __shared__ float h_s[H];
    __shared__ float x_s[H];
    __shared__ float acc_x[NWARP];
    __shared__ float acc_h[NWARP];
    __shared__ int   L_s[BS];

    const int tid   = threadIdx.x;
    const int w     = tid >> 5;
    const int lane  = tid & 31;
    const int hbase = blockIdx.x * HPC;
    const int g     = w / HPC;
    const int j     = w % HPC;
    const int row   = g * H + hbase + j;

    // --- load this warp's weight rows into registers (persists whole launch) ---
    float4 wih[6], whh[6];
    const float4* Wih4 = (const float4*)(Wih + (size_t)row * H);
    const float4* Whh4 = (const float4*)(Whh + (size_t)row * H);
    #pragma unroll
    for (int i = 0; i < 6; i++) {
        wih[i] = Wih4[lane + 32 * i];
        whh[i] = Whh4[lane + 32 * i];
    }
    const float bi = bih[row];
    const float bh = bhh[row];

    // --- init: lengths, h0 = global_context, x = emb[0,0,:] ---
    if (tid < BS) L_s[tid] = g_L[tid];
    for (int i = tid; i < H; i += NTHR) { h_s[i] = gc[i]; x_s[i] = emb[i]; }
    __syncthreads();

    const float4* h4 = (const float4*)h_s;
    const float4* x4 = (const float4*)x_s;

    int b = 0, t = 0;
    unsigned s = 0;  // global step index (same on every CTA)

    while (true) {
        // ---- fused matvec: ax = dot(Wih_row, x), ah = dot(Whh_row, h) ----
        float ax = 0.f, ah = 0.f;
        #pragma unroll
        for (int i = 0; i < 6; i++) {
            float4 xv = x4[lane + 32 * i];
            float4 hv = h4[lane + 32 * i];
            ax = fmaf(wih[i].x, xv.x, ax);
            ax = fmaf(wih[i].y, xv.y, ax);
            ax = fmaf(wih[i].z, xv.z, ax);
            ax = fmaf(wih[i].w, xv.w, ax);
            ah = fmaf(whh[i].x, hv.x, ah);
            ah = fmaf(whh[i].y, hv.y, ah);
            ah = fmaf(whh[i].z, hv.z, ah);
            ah = fmaf(whh[i].w, hv.w, ah);
        }
        #pragma unroll
        for (int m = 16; m; m >>= 1) {
            ax += __shfl_xor_sync(~0u, ax, m);
            ah += __shfl_xor_sync(~0u, ah, m);
        }
        if (lane == 0) { acc_x[w] = ax + bi; acc_h[w] = ah + bh; }
        __syncthreads();

        const int Lb = L_s[b];
        const int wp = (s + 1) & 1;  // write parity

        if (w == 0) {
            if (lane < HPC) {
                // gate combine for h-index hbase+lane
                float r  = 1.f / (1.f + expf(-(acc_x[lane]         + acc_h[lane])));
                float z  = 1.f / (1.f + expf(-(acc_x[HPC + lane]   + acc_h[HPC + lane])));
                float n  = tanhf(acc_x[2 * HPC + lane] + r * acc_h[2 * HPC + lane]);
                float hn = (1.f - z) * n + z * h_s[hbase + lane];
                __stcg(&g_hbuf[wp][hbase + lane], hn);   // L2-visible write
                if (t == Lb - 1) {
                    // outputs[b] = final hidden of sample b
                    if (out_size >= BS * H)
                        out[(size_t)b * H + hbase + lane] = hn;
                    // trailing detached context (= outputs[BS-1]) if requested
                    if (out_size >= BS * H + H && b == BS - 1)
                        out[BS * H + hbase + lane] = hn;
                    if (out_size == H && b == BS - 1)
                        out[hbase + lane] = hn;
                }
            }
            __syncwarp();
            if (lane == 0) {
                __threadfence();                 // publish h slice
                atomicAdd(&g_ctr, 1u);           // arrive
                const unsigned target = (s + 1) * GRID;
                while (*(volatile unsigned*)&g_ctr < target) { }
                __threadfence();                 // acquire side
            }
        }
        __syncthreads();  // all threads wait for barrier completion

        // ---- advance (identical control flow on every CTA) ----
        t++;
        if (t >= Lb) { t = 0; b++; }
        if (b >= BS) break;

        const float* xsrc = emb + ((size_t)b * T + t) * H;
        for (int i = tid; i < H; i += NTHR) {
            h_s[i] = __ldcg(&g_hbuf[wp][i]);     // L2-coherent read (skip stale L1)
            x_s[i] = xsrc[i];
        }
        s++;
        __syncthreads();
    }
}

// ---------------------------------------------------------------------------
// Launch. Inputs (metadata order): embedding f32[32,512,768], attention_mask
// int32[32,512] (JAX demotes int64), global_context f32[1,1,768],
// W_ih f32[2304,768], W_hh f32[2304,768], b_ih f32[2304], b_hh f32[2304].
// ---------------------------------------------------------------------------
extern "C" void kernel_launch(void* const* d_in, const int* in_sizes, int n_in,
                              void* d_out, int out_size)
{
    const float* emb  = (const float*)d_in[0];
    const int*   mask = (const int*)d_in[1];
    const float* gc   = (const float*)d_in[2];
    const float* Wih  = (const float*)d_in[3];
    const float* Whh  = (const float*)d_in[4];
    const float* bih  = (const float*)d_in[5];
    const float* bhh  = (const float*)d_in[6];
    float* out = (float*)d_out;

    compute_L_kernel<<<1, 1024>>>(mask);
    gru_kernel<<<GRID, NTHR>>>(emb, gc, Wih, Whh, bih, bhh, out, out_size);
}